// round 1
// baseline (speedup 1.0000x reference)
#include <cuda_runtime.h>
#include <math.h>

// ---------------------------------------------------------------------------
// Problem constants
// ---------------------------------------------------------------------------
#define B_    4
#define NLAT  512
#define NCTX  4096
#define DIMM  512
#define HEADS 8
#define DHEAD 64
#define NTOT  (NLAT + NCTX)        // 4608
#define ROWS_KV (B_ * NTOT)        // 18432
#define ROWS_Q  (B_ * NLAT)        // 2048

// ---------------------------------------------------------------------------
// Scratch (device globals: allocation-free rule)
// ---------------------------------------------------------------------------
__device__ float g_K[(size_t)ROWS_KV * DIMM];   // [b][m][h*d]  37.75 MB
__device__ float g_V[(size_t)ROWS_KV * DIMM];   // [b][m][h*d]  37.75 MB
__device__ float g_Q[(size_t)ROWS_Q  * DIMM];   // [b][n][h*d]   4 MB
__device__ float g_O[(size_t)ROWS_Q  * DIMM];   // [b][n][h*d]   4 MB

// ---------------------------------------------------------------------------
// SGEMM-NT: C[M][N] = A[M][K] * W[N][K]^T   (both K-contiguous)
// 128x128 block tile, BK=16, 256 threads, 8x8 per-thread micro-tile.
// MODE 0: A = x (param A0),  C = g_Q
// MODE 1: A = concat(x, context) gathered per row, C split into g_K / g_V
// MODE 2: A = g_O (internal), C = param C (final output)
// ---------------------------------------------------------------------------
#define BM 128
#define BN 128
#define BK 16
#define PADM 132

template<int MODE>
__global__ __launch_bounds__(256, 2) void sgemm_nt(
    const float* __restrict__ A0,   // x (MODE 0/1) / unused (MODE 2)
    const float* __restrict__ A1,   // context (MODE 1 only)
    const float* __restrict__ W,    // [N][K]
    float* __restrict__ C,          // MODE 2 only
    int N, int K)
{
    __shared__ float As[BK][PADM];
    __shared__ float Bs[BK][PADM];

    const int tid  = threadIdx.x;
    const int tx   = tid & 15;
    const int ty   = tid >> 4;
    const int brow = blockIdx.y * BM;
    const int bcol = blockIdx.x * BN;
    const int lrow = tid >> 2;           // 0..63
    const int lk   = (tid & 3) << 2;     // 0,4,8,12

    // Resolve A row pointers (loop-invariant)
    const float* pa0;
    const float* pa1;
    {
        const int r0 = brow + lrow;
        const int r1 = r0 + 64;
        if (MODE == 1) {
            int b0 = r0 / NTOT, m0 = r0 - b0 * NTOT;
            pa0 = (m0 < NLAT) ? A0 + ((size_t)(b0 * NLAT + m0)) * DIMM
                              : A1 + ((size_t)b0 * NCTX + (m0 - NLAT)) * DIMM;
            int b1 = r1 / NTOT, m1 = r1 - b1 * NTOT;
            pa1 = (m1 < NLAT) ? A0 + ((size_t)(b1 * NLAT + m1)) * DIMM
                              : A1 + ((size_t)b1 * NCTX + (m1 - NLAT)) * DIMM;
        } else if (MODE == 2) {
            pa0 = g_O + (size_t)r0 * K;
            pa1 = g_O + (size_t)r1 * K;
        } else {
            pa0 = A0 + (size_t)r0 * K;
            pa1 = A0 + (size_t)r1 * K;
        }
    }
    const float* pw0 = W + (size_t)(bcol + lrow) * K;
    const float* pw1 = pw0 + (size_t)64 * K;

    float acc[8][8];
#pragma unroll
    for (int i = 0; i < 8; i++)
#pragma unroll
        for (int j = 0; j < 8; j++) acc[i][j] = 0.0f;

    for (int k0 = 0; k0 < K; k0 += BK) {
        // Stage global loads in registers before the barrier
        float4 a0 = *(const float4*)(pa0 + k0 + lk);
        float4 a1 = *(const float4*)(pa1 + k0 + lk);
        float4 w0 = *(const float4*)(pw0 + k0 + lk);
        float4 w1 = *(const float4*)(pw1 + k0 + lk);

        __syncthreads();   // protect previous iteration's smem reads
        As[lk + 0][lrow] = a0.x; As[lk + 1][lrow] = a0.y;
        As[lk + 2][lrow] = a0.z; As[lk + 3][lrow] = a0.w;
        As[lk + 0][lrow + 64] = a1.x; As[lk + 1][lrow + 64] = a1.y;
        As[lk + 2][lrow + 64] = a1.z; As[lk + 3][lrow + 64] = a1.w;
        Bs[lk + 0][lrow] = w0.x; Bs[lk + 1][lrow] = w0.y;
        Bs[lk + 2][lrow] = w0.z; Bs[lk + 3][lrow] = w0.w;
        Bs[lk + 0][lrow + 64] = w1.x; Bs[lk + 1][lrow + 64] = w1.y;
        Bs[lk + 2][lrow + 64] = w1.z; Bs[lk + 3][lrow + 64] = w1.w;
        __syncthreads();

#pragma unroll
        for (int kk = 0; kk < BK; kk++) {
            float4 aA = *(const float4*)&As[kk][ty * 4];
            float4 aB = *(const float4*)&As[kk][64 + ty * 4];
            float4 bA = *(const float4*)&Bs[kk][tx * 4];
            float4 bB = *(const float4*)&Bs[kk][64 + tx * 4];
            float a[8] = {aA.x, aA.y, aA.z, aA.w, aB.x, aB.y, aB.z, aB.w};
            float b[8] = {bA.x, bA.y, bA.z, bA.w, bB.x, bB.y, bB.z, bB.w};
#pragma unroll
            for (int i = 0; i < 8; i++)
#pragma unroll
                for (int j = 0; j < 8; j++) acc[i][j] += a[i] * b[j];
        }
    }

    // Epilogue
#pragma unroll
    for (int i = 0; i < 8; i++) {
        const int r = brow + ((i < 4) ? (ty * 4 + i) : (64 + ty * 4 + i - 4));
#pragma unroll
        for (int jq = 0; jq < 2; jq++) {
            const int c = bcol + jq * 64 + tx * 4;
            float4 v = make_float4(acc[i][jq * 4 + 0], acc[i][jq * 4 + 1],
                                   acc[i][jq * 4 + 2], acc[i][jq * 4 + 3]);
            if (MODE == 1) {
                float* dst = (c < DIMM) ? g_K : g_V;
                const int cc = c & (DIMM - 1);
                *(float4*)(dst + (size_t)r * DIMM + cc) = v;
            } else if (MODE == 0) {
                *(float4*)(g_Q + (size_t)r * N + c) = v;
            } else {
                *(float4*)(C + (size_t)r * N + c) = v;
            }
        }
    }
}

// ---------------------------------------------------------------------------
// Flash attention: one block per (q-block of 64, head, batch).
// Br = Bc = 64, d = 64. 256 threads in 16x16, 4x4 micro-tiles.
// Smem (dynamic, 66 KB):
//   Qs [64][64]  natural  [r][d]   (prescaled by 1/8)
//   Ks [64][68]  transposed [d][m] (pad 68 kills transpose-store conflicts)
//   Vs [64][64]  natural  [m][d]
//   Ps [64][68]  natural  [r][c]
// All inner-loop LDS.128 are conflict-free by construction.
// ---------------------------------------------------------------------------
#define QS_OFF 0
#define KS_OFF 4096
#define VS_OFF (4096 + 4352)
#define PS_OFF (4096 + 4352 + 4096)
#define FLASH_SMEM ((4096 + 4352 + 4096 + 4352) * 4)

__global__ __launch_bounds__(256, 2) void flash_kernel()
{
    extern __shared__ float sm[];
    float* Qs = sm + QS_OFF;
    float* Ks = sm + KS_OFF;
    float* Vs = sm + VS_OFF;
    float* Ps = sm + PS_OFF;

    const int tid = threadIdx.x;
    const int tx  = tid & 15;
    const int ty  = tid >> 4;
    const int qb  = blockIdx.x;
    const int h   = blockIdx.y;
    const int b   = blockIdx.z;

    const float scale = 0.125f;   // 1/sqrt(64)
    const float* Qg = g_Q + ((size_t)(b * NLAT + qb * 64)) * DIMM + h * DHEAD;
    const float* Kg = g_K + ((size_t)b * NTOT) * DIMM + h * DHEAD;
    const float* Vg = g_V + ((size_t)b * NTOT) * DIMM + h * DHEAD;

    // Load + prescale Q tile (natural [r][d])
#pragma unroll
    for (int q = 0; q < 4; q++) {
        const int f  = tid + q * 256;
        const int r  = f >> 4;
        const int d4 = (f & 15) << 2;
        float4 v = *(const float4*)(Qg + (size_t)r * DIMM + d4);
        v.x *= scale; v.y *= scale; v.z *= scale; v.w *= scale;
        *(float4*)&Qs[r * 64 + d4] = v;
    }

    float m_i[4], l_i[4], o[4][4];
#pragma unroll
    for (int i = 0; i < 4; i++) {
        m_i[i] = -INFINITY;
        l_i[i] = 0.0f;
#pragma unroll
        for (int j = 0; j < 4; j++) o[i][j] = 0.0f;
    }

    for (int t = 0; t < NTOT / 64; t++) {
        // Stage K/V tile loads in registers
        float4 kv[4], vv[4];
#pragma unroll
        for (int q = 0; q < 4; q++) {
            const int f  = tid + q * 256;
            const int mm = f >> 4;
            const int d4 = (f & 15) << 2;
            kv[q] = *(const float4*)(Kg + (size_t)(t * 64 + mm) * DIMM + d4);
            vv[q] = *(const float4*)(Vg + (size_t)(t * 64 + mm) * DIMM + d4);
        }
        __syncthreads();   // previous tile's PV reads done
#pragma unroll
        for (int q = 0; q < 4; q++) {
            const int f  = tid + q * 256;
            const int mm = f >> 4;
            const int d4 = (f & 15) << 2;
            Ks[(d4 + 0) * 68 + mm] = kv[q].x;
            Ks[(d4 + 1) * 68 + mm] = kv[q].y;
            Ks[(d4 + 2) * 68 + mm] = kv[q].z;
            Ks[(d4 + 3) * 68 + mm] = kv[q].w;
            *(float4*)&Vs[mm * 64 + d4] = vv[q];
        }
        __syncthreads();

        // S = Q @ K^T (reduction over d)
        float s[4][4];
#pragma unroll
        for (int i = 0; i < 4; i++)
#pragma unroll
            for (int j = 0; j < 4; j++) s[i][j] = 0.0f;

#pragma unroll
        for (int k4 = 0; k4 < 16; k4++) {
            float a2[4][4];
#pragma unroll
            for (int i = 0; i < 4; i++) {
                float4 t4 = *(const float4*)&Qs[(ty * 4 + i) * 64 + k4 * 4];
                a2[i][0] = t4.x; a2[i][1] = t4.y; a2[i][2] = t4.z; a2[i][3] = t4.w;
            }
#pragma unroll
            for (int c = 0; c < 4; c++) {
                float4 bb = *(const float4*)&Ks[(k4 * 4 + c) * 68 + tx * 4];
#pragma unroll
                for (int i = 0; i < 4; i++) {
                    s[i][0] += a2[i][c] * bb.x;
                    s[i][1] += a2[i][c] * bb.y;
                    s[i][2] += a2[i][c] * bb.z;
                    s[i][3] += a2[i][c] * bb.w;
                }
            }
        }

        // Online softmax (row groups = 16 lanes sharing ty)
#pragma unroll
        for (int i = 0; i < 4; i++) {
            float tm = fmaxf(fmaxf(s[i][0], s[i][1]), fmaxf(s[i][2], s[i][3]));
#pragma unroll
            for (int off = 8; off > 0; off >>= 1)
                tm = fmaxf(tm, __shfl_xor_sync(0xffffffffu, tm, off));
            const float nm   = fmaxf(m_i[i], tm);
            const float corr = __expf(m_i[i] - nm);
            m_i[i] = nm;
            float rs = 0.0f;
#pragma unroll
            for (int j = 0; j < 4; j++) {
                s[i][j] = __expf(s[i][j] - nm);
                rs += s[i][j];
            }
#pragma unroll
            for (int off = 8; off > 0; off >>= 1)
                rs += __shfl_xor_sync(0xffffffffu, rs, off);
            l_i[i] = l_i[i] * corr + rs;
#pragma unroll
            for (int j = 0; j < 4; j++) o[i][j] *= corr;
        }

        // P -> smem (natural [r][c], float4, conflict-free)
#pragma unroll
        for (int i = 0; i < 4; i++)
            *(float4*)&Ps[(ty * 4 + i) * 68 + tx * 4] =
                make_float4(s[i][0], s[i][1], s[i][2], s[i][3]);
        __syncthreads();

        // O += P @ V (reduction over c)
#pragma unroll
        for (int c4 = 0; c4 < 16; c4++) {
            float a2[4][4];
#pragma unroll
            for (int i = 0; i < 4; i++) {
                float4 t4 = *(const float4*)&Ps[(ty * 4 + i) * 68 + c4 * 4];
                a2[i][0] = t4.x; a2[i][1] = t4.y; a2[i][2] = t4.z; a2[i][3] = t4.w;
            }
#pragma unroll
            for (int c = 0; c < 4; c++) {
                float4 bb = *(const float4*)&Vs[(c4 * 4 + c) * 64 + tx * 4];
#pragma unroll
                for (int i = 0; i < 4; i++) {
                    o[i][0] += a2[i][c] * bb.x;
                    o[i][1] += a2[i][c] * bb.y;
                    o[i][2] += a2[i][c] * bb.z;
                    o[i][3] += a2[i][c] * bb.w;
                }
            }
        }
    }

    // Normalize and write O (b n (h d) layout, float4)
#pragma unroll
    for (int i = 0; i < 4; i++) {
        const float inv = 1.0f / l_i[i];
        float4 v = make_float4(o[i][0] * inv, o[i][1] * inv,
                               o[i][2] * inv, o[i][3] * inv);
        *(float4*)(g_O + ((size_t)(b * NLAT + qb * 64 + ty * 4 + i)) * DIMM
                   + h * DHEAD + tx * 4) = v;
    }
}

// ---------------------------------------------------------------------------
// Launch
// ---------------------------------------------------------------------------
extern "C" void kernel_launch(void* const* d_in, const int* in_sizes, int n_in,
                              void* d_out, int out_size)
{
    const float* x    = (const float*)d_in[0];
    const float* ctx  = (const float*)d_in[1];
    const float* Wq   = (const float*)d_in[2];
    const float* Wkv  = (const float*)d_in[3];
    const float* Wout = (const float*)d_in[4];
    float* out = (float*)d_out;

    cudaFuncSetAttribute(flash_kernel,
                         cudaFuncAttributeMaxDynamicSharedMemorySize, FLASH_SMEM);

    // KV projection: [18432, 512] @ Wkv^T -> g_K, g_V
    sgemm_nt<1><<<dim3(1024 / BN, ROWS_KV / BM), 256>>>(x, ctx, Wkv, nullptr, 1024, DIMM);
    // Q projection: [2048, 512] @ Wq^T -> g_Q
    sgemm_nt<0><<<dim3(512 / BN, ROWS_Q / BM), 256>>>(x, nullptr, Wq, nullptr, 512, DIMM);
    // Attention -> g_O
    flash_kernel<<<dim3(NLAT / 64, HEADS, B_), 256, FLASH_SMEM>>>();
    // Output projection: g_O @ Wout^T -> out
    sgemm_nt<2><<<dim3(512 / BN, ROWS_Q / BM), 256>>>(nullptr, nullptr, Wout, out, 512, DIMM);
}

// round 15
// speedup vs baseline: 1.9109x; 1.9109x over previous
#include <cuda_runtime.h>
#include <cuda_bf16.h>
#include <math.h>
#include <cstdint>

// ---------------------------------------------------------------------------
// Problem constants
// ---------------------------------------------------------------------------
#define B_    4
#define NLAT  512
#define NCTX  4096
#define DIMM  512
#define HEADS 8
#define DHEAD 64
#define NTOT  (NLAT + NCTX)        // 4608
#define ROWS_KV (B_ * NTOT)        // 18432
#define ROWS_Q  (B_ * NLAT)        // 2048

// ---------------------------------------------------------------------------
// Scratch (device globals: allocation-free rule)
// ---------------------------------------------------------------------------
__device__ float g_K[(size_t)ROWS_KV * DIMM];
__device__ float g_V[(size_t)ROWS_KV * DIMM];
__device__ float g_Q[(size_t)ROWS_Q  * DIMM];
__device__ float g_O[(size_t)ROWS_Q  * DIMM];

// ---------------------------------------------------------------------------
// Baseline-ISA tensor-core helpers (valid on compute_103 WITHOUT 'a' suffix):
// ldmatrix (sm_75+), mma.sync bf16 (sm_80+). NO tcgen05/TMEM anywhere.
// ---------------------------------------------------------------------------
__device__ __forceinline__ uint32_t smem_u32(const void* p) {
    uint32_t a;
    asm("{ .reg .u64 t; cvta.to.shared.u64 t, %1; cvt.u32.u64 %0, t; }"
        : "=r"(a) : "l"(p));
    return a;
}
__device__ __forceinline__ void ldsm_x4(uint32_t& r0, uint32_t& r1,
                                        uint32_t& r2, uint32_t& r3, uint32_t addr) {
    asm volatile("ldmatrix.sync.aligned.m8n8.x4.shared.b16 {%0,%1,%2,%3}, [%4];"
                 : "=r"(r0), "=r"(r1), "=r"(r2), "=r"(r3) : "r"(addr));
}
__device__ __forceinline__ void mma_16816(float* c, const uint32_t* a,
                                          uint32_t b0, uint32_t b1) {
    asm volatile(
        "mma.sync.aligned.m16n8k16.row.col.f32.bf16.bf16.f32 "
        "{%0,%1,%2,%3}, {%4,%5,%6,%7}, {%8,%9}, {%0,%1,%2,%3};"
        : "+f"(c[0]), "+f"(c[1]), "+f"(c[2]), "+f"(c[3])
        : "r"(a[0]), "r"(a[1]), "r"(a[2]), "r"(a[3]), "r"(b0), "r"(b1));
}
// fp32 -> bf16 hi/lo split, 4 lanes packed as 2x uint2
__device__ __forceinline__ void cvt_hilo4(float4 v, uint2& h, uint2& l) {
    __nv_bfloat162 h01 = __floats2bfloat162_rn(v.x, v.y);
    __nv_bfloat162 h23 = __floats2bfloat162_rn(v.z, v.w);
    __nv_bfloat162 l01 = __floats2bfloat162_rn(v.x - __bfloat162float(h01.x),
                                               v.y - __bfloat162float(h01.y));
    __nv_bfloat162 l23 = __floats2bfloat162_rn(v.z - __bfloat162float(h23.x),
                                               v.w - __bfloat162float(h23.y));
    h = make_uint2(*(uint32_t*)&h01, *(uint32_t*)&h23);
    l = make_uint2(*(uint32_t*)&l01, *(uint32_t*)&l23);
}
__device__ __forceinline__ void pack_hilo2(float a, float b, uint32_t& h, uint32_t& l) {
    __nv_bfloat162 hp = __floats2bfloat162_rn(a, b);
    __nv_bfloat162 lp = __floats2bfloat162_rn(a - __bfloat162float(hp.x),
                                              b - __bfloat162float(hp.y));
    h = *(uint32_t*)&hp;
    l = *(uint32_t*)&lp;
}

// ---------------------------------------------------------------------------
// mma.sync GEMM (bf16 hi/lo x3):  C[M][N] = A[M][K=512] * W[N][K=512]^T
// CTA tile 128x128, 256 threads = 8 warps (4 m-rows x 2 n-cols),
// warp tile 32x64, BK=64, k-inner steps of 16.
// Smem: bf16 tiles with 72-element (144B) row pitch -> ldmatrix conflict-free.
// ---------------------------------------------------------------------------
#define PITCH_B 144          // bytes per smem row (72 bf16)
#define SA_H 0
#define SA_L 18432
#define SB_H 36864
#define SB_L 55296
#define MM_SMEM 73728
#define KTILES 8             // 512 / 64

template<int MODE>
__global__ __launch_bounds__(256, 1) void mm_gemm(
    const float* __restrict__ A0,
    const float* __restrict__ A1,
    const float* __restrict__ W,
    float* __restrict__ C)
{
    extern __shared__ __align__(16) char sm[];
    const int tid    = threadIdx.x;
    const int lane   = tid & 31;
    const int wid    = tid >> 5;
    const int warp_m = wid & 3;
    const int warp_n = wid >> 2;
    const int brow   = blockIdx.y * 128;
    const int bcol   = blockIdx.x * 128;

    const float* rowA[8];
    uint32_t     offB[8];
    uint32_t     stOff[8];
#pragma unroll
    for (int i = 0; i < 8; i++) {
        const int idx = i * 256 + tid;
        const int r   = idx >> 4;
        const int c4  = idx & 15;
        const int gr  = brow + r;
        if (MODE == 1) {
            const int b = gr / NTOT, m = gr - b * NTOT;
            rowA[i] = (m < NLAT) ? A0 + ((size_t)(b * NLAT + m)) * DIMM
                                 : A1 + ((size_t)b * NCTX + (m - NLAT)) * DIMM;
        } else if (MODE == 2) {
            rowA[i] = g_O + (size_t)gr * DIMM;
        } else {
            rowA[i] = A0 + (size_t)gr * DIMM;
        }
        rowA[i] += c4 * 4;
        offB[i]  = (uint32_t)(bcol + r) * DIMM + c4 * 4;
        stOff[i] = (uint32_t)r * PITCH_B + c4 * 8;
    }

    const uint32_t sbase = smem_u32(sm);
    const int aRow  = warp_m * 32 + (lane & 7) + 8 * ((lane >> 3) & 1);
    const int aKoff = (lane >> 4) * 16;
    const int bRow  = warp_n * 64 + (lane & 7) + 8 * (lane >> 4);
    const int bKoff = ((lane >> 3) & 1) * 16;

    float acc[2][8][4];
#pragma unroll
    for (int mt = 0; mt < 2; mt++)
#pragma unroll
        for (int nt = 0; nt < 8; nt++)
#pragma unroll
            for (int j = 0; j < 4; j++) acc[mt][nt][j] = 0.0f;

    for (int kt = 0; kt < KTILES; kt++) {
        const int ko = kt * 64;
        float4 av[8], bv[8];
#pragma unroll
        for (int i = 0; i < 8; i++) av[i] = *(const float4*)(rowA[i] + ko);
#pragma unroll
        for (int i = 0; i < 8; i++) bv[i] = *(const float4*)(W + offB[i] + ko);

        __syncthreads();
#pragma unroll
        for (int i = 0; i < 8; i++) {
            uint2 h, l;
            cvt_hilo4(av[i], h, l);
            *(uint2*)(sm + SA_H + stOff[i]) = h;
            *(uint2*)(sm + SA_L + stOff[i]) = l;
        }
#pragma unroll
        for (int i = 0; i < 8; i++) {
            uint2 h, l;
            cvt_hilo4(bv[i], h, l);
            *(uint2*)(sm + SB_H + stOff[i]) = h;
            *(uint2*)(sm + SB_L + stOff[i]) = l;
        }
        __syncthreads();

#pragma unroll
        for (int ks = 0; ks < 4; ks++) {
            const int kb = ks * 32;
            uint32_t ahi[2][4], alo[2][4];
#pragma unroll
            for (int mt = 0; mt < 2; mt++) {
                const uint32_t ra = (uint32_t)(aRow + mt * 16) * PITCH_B + aKoff + kb;
                ldsm_x4(ahi[mt][0], ahi[mt][1], ahi[mt][2], ahi[mt][3],
                        sbase + SA_H + ra);
                ldsm_x4(alo[mt][0], alo[mt][1], alo[mt][2], alo[mt][3],
                        sbase + SA_L + ra);
            }
            uint32_t bhi[4][4], blo[4][4];
#pragma unroll
            for (int ng = 0; ng < 4; ng++) {
                const uint32_t rb = (uint32_t)(bRow + ng * 16) * PITCH_B + bKoff + kb;
                ldsm_x4(bhi[ng][0], bhi[ng][1], bhi[ng][2], bhi[ng][3],
                        sbase + SB_H + rb);
                ldsm_x4(blo[ng][0], blo[ng][1], blo[ng][2], blo[ng][3],
                        sbase + SB_L + rb);
            }
#pragma unroll
            for (int mt = 0; mt < 2; mt++)
#pragma unroll
                for (int nt = 0; nt < 8; nt++) {
                    const int ng = nt >> 1;
                    const int rp = (nt & 1) * 2;
                    mma_16816(acc[mt][nt], ahi[mt], bhi[ng][rp], bhi[ng][rp + 1]);
                    mma_16816(acc[mt][nt], ahi[mt], blo[ng][rp], blo[ng][rp + 1]);
                    mma_16816(acc[mt][nt], alo[mt], bhi[ng][rp], bhi[ng][rp + 1]);
                }
        }
    }

#pragma unroll
    for (int mt = 0; mt < 2; mt++) {
        const int m0 = brow + warp_m * 32 + mt * 16 + (lane >> 2);
#pragma unroll
        for (int nt = 0; nt < 8; nt++) {
            const int n0 = bcol + warp_n * 64 + nt * 8 + (lane & 3) * 2;
            float* dst;
            if (MODE == 1) {
                float* base = (n0 < DIMM) ? g_K : g_V;
                dst = base + (n0 & (DIMM - 1));
            } else if (MODE == 0) {
                dst = g_Q + n0;
            } else {
                dst = C + n0;
            }
            *(float2*)(dst + (size_t)m0 * DIMM) =
                make_float2(acc[mt][nt][0], acc[mt][nt][1]);
            *(float2*)(dst + (size_t)(m0 + 8) * DIMM) =
                make_float2(acc[mt][nt][2], acc[mt][nt][3]);
        }
    }
}

// ---------------------------------------------------------------------------
// Flash attention with mma.sync (bf16 hi/lo x3 for BOTH GEMMs).
// One CTA per (64 q-rows, head, batch); 128 threads = 4 warps, 16 rows/warp.
// Per kv-tile (64): S = Q·K^T via mma (K as audited non-trans B operand),
// online softmax on C fragments (quad shfl), P reused in-register as A
// fragment (C->A identity), P·V via mma with V TRANSPOSED AT STAGING so the
// B operand is the same audited non-trans path.
// Smem: KH|KL|VH|VL, each 64 rows x 144B pitch = 9216 B -> 36864 B total.
// ---------------------------------------------------------------------------
#define FKH 0
#define FKL 9216
#define FVH 18432
#define FVL 27648
#define FLASH_SMEM 36864

__global__ __launch_bounds__(128, 1) void flash_mma()
{
    extern __shared__ __align__(16) char sm[];
    const uint32_t sbase = smem_u32(sm);
    const int tid  = threadIdx.x;
    const int lane = tid & 31;
    const int warp = tid >> 5;
    const int qb = blockIdx.x, h = blockIdx.y, b = blockIdx.z;

    const float* Qg = g_Q + ((size_t)(b * NLAT + qb * 64)) * DIMM + h * DHEAD;
    const float* Kg = g_K + ((size_t)b * NTOT) * DIMM + h * DHEAD;
    const float* Vg = g_V + ((size_t)b * NTOT) * DIMM + h * DHEAD;

    // ---- stage Q (prescaled by 1/8) into KH/KL, load A fragments ----
#pragma unroll
    for (int i = 0; i < 8; i++) {
        const int f  = i * 128 + tid;
        const int r  = f >> 4;
        const int c4 = f & 15;
        float4 v = *(const float4*)(Qg + (size_t)r * DIMM + c4 * 4);
        v.x *= 0.125f; v.y *= 0.125f; v.z *= 0.125f; v.w *= 0.125f;
        uint2 hh, ll;
        cvt_hilo4(v, hh, ll);
        *(uint2*)(sm + FKH + (uint32_t)r * PITCH_B + c4 * 8) = hh;
        *(uint2*)(sm + FKL + (uint32_t)r * PITCH_B + c4 * 8) = ll;
    }
    __syncthreads();

    const int aR = warp * 16 + (lane & 7) + 8 * ((lane >> 3) & 1);
    const int aK = (lane >> 4) * 16;
    uint32_t qhi[4][4], qlo[4][4];
#pragma unroll
    for (int kf = 0; kf < 4; kf++) {
        const uint32_t ra = (uint32_t)aR * PITCH_B + aK + kf * 32;
        ldsm_x4(qhi[kf][0], qhi[kf][1], qhi[kf][2], qhi[kf][3], sbase + FKH + ra);
        ldsm_x4(qlo[kf][0], qlo[kf][1], qlo[kf][2], qlo[kf][3], sbase + FKL + ra);
    }

    const int bR = (lane & 7) + 8 * (lane >> 4);   // row-in-16 for B loads
    const int bK = ((lane >> 3) & 1) * 16;

    float m0 = -INFINITY, m1 = -INFINITY, l0 = 0.0f, l1 = 0.0f;
    float o[8][4];
#pragma unroll
    for (int nt = 0; nt < 8; nt++)
#pragma unroll
        for (int j = 0; j < 4; j++) o[nt][j] = 0.0f;

    for (int t = 0; t < NTOT / 64; t++) {
        // stage K/V gmem loads
        float4 kv[8], vv[8];
#pragma unroll
        for (int i = 0; i < 8; i++) {
            const int f  = i * 128 + tid;
            const int r  = f >> 4;
            const int c4 = f & 15;
            kv[i] = *(const float4*)(Kg + (size_t)(t * 64 + r) * DIMM + c4 * 4);
            vv[i] = *(const float4*)(Vg + (size_t)(t * 64 + r) * DIMM + c4 * 4);
        }
        __syncthreads();   // previous tile's ldsm reads (and t=0: Q ldsm) done
#pragma unroll
        for (int i = 0; i < 8; i++) {
            const int f  = i * 128 + tid;
            const int r  = f >> 4;
            const int c4 = f & 15;
            // K: rows n=r, cols d (audited GEMM-B layout)
            uint2 hh, ll;
            cvt_hilo4(kv[i], hh, ll);
            *(uint2*)(sm + FKH + (uint32_t)r * PITCH_B + c4 * 8) = hh;
            *(uint2*)(sm + FKL + (uint32_t)r * PITCH_B + c4 * 8) = ll;
            // V^T: rows d=c4*4+j, col c=r (transpose at staging)
            float vals[4] = {vv[i].x, vv[i].y, vv[i].z, vv[i].w};
#pragma unroll
            for (int j = 0; j < 4; j++) {
                __nv_bfloat16 hb = __float2bfloat16_rn(vals[j]);
                __nv_bfloat16 lb = __float2bfloat16_rn(vals[j] - __bfloat162float(hb));
                *(__nv_bfloat16*)(sm + FVH + (uint32_t)(c4 * 4 + j) * PITCH_B + r * 2) = hb;
                *(__nv_bfloat16*)(sm + FVL + (uint32_t)(c4 * 4 + j) * PITCH_B + r * 2) = lb;
            }
        }
        __syncthreads();

        // ---- S = Q K^T (hi/lo x3) ----
        float s[8][4];
#pragma unroll
        for (int nt = 0; nt < 8; nt++)
#pragma unroll
            for (int j = 0; j < 4; j++) s[nt][j] = 0.0f;

#pragma unroll
        for (int kf = 0; kf < 4; kf++) {
            uint32_t bh[4][4], bl[4][4];
#pragma unroll
            for (int g = 0; g < 4; g++) {
                const uint32_t rb = (uint32_t)(g * 16 + bR) * PITCH_B + bK + kf * 32;
                ldsm_x4(bh[g][0], bh[g][1], bh[g][2], bh[g][3], sbase + FKH + rb);
                ldsm_x4(bl[g][0], bl[g][1], bl[g][2], bl[g][3], sbase + FKL + rb);
            }
#pragma unroll
            for (int nt = 0; nt < 8; nt++) {
                const int ng = nt >> 1;
                const int rp = (nt & 1) * 2;
                mma_16816(s[nt], qhi[kf], bh[ng][rp], bh[ng][rp + 1]);
                mma_16816(s[nt], qhi[kf], bl[ng][rp], bl[ng][rp + 1]);
                mma_16816(s[nt], qlo[kf], bh[ng][rp], bh[ng][rp + 1]);
            }
        }

        // ---- online softmax (rows r0=lane>>2, r1=r0+8; quad = lanes xor 1,2) ----
        float tm0 = -INFINITY, tm1 = -INFINITY;
#pragma unroll
        for (int nt = 0; nt < 8; nt++) {
            tm0 = fmaxf(tm0, fmaxf(s[nt][0], s[nt][1]));
            tm1 = fmaxf(tm1, fmaxf(s[nt][2], s[nt][3]));
        }
        tm0 = fmaxf(tm0, __shfl_xor_sync(0xffffffffu, tm0, 1));
        tm0 = fmaxf(tm0, __shfl_xor_sync(0xffffffffu, tm0, 2));
        tm1 = fmaxf(tm1, __shfl_xor_sync(0xffffffffu, tm1, 1));
        tm1 = fmaxf(tm1, __shfl_xor_sync(0xffffffffu, tm1, 2));

        const float nm0 = fmaxf(m0, tm0);
        const float nm1 = fmaxf(m1, tm1);
        const float c0 = __expf(m0 - nm0);
        const float c1 = __expf(m1 - nm1);
        m0 = nm0; m1 = nm1;

        float rs0 = 0.0f, rs1 = 0.0f;
#pragma unroll
        for (int nt = 0; nt < 8; nt++) {
            s[nt][0] = __expf(s[nt][0] - nm0);
            s[nt][1] = __expf(s[nt][1] - nm0);
            s[nt][2] = __expf(s[nt][2] - nm1);
            s[nt][3] = __expf(s[nt][3] - nm1);
            rs0 += s[nt][0] + s[nt][1];
            rs1 += s[nt][2] + s[nt][3];
        }
        rs0 += __shfl_xor_sync(0xffffffffu, rs0, 1);
        rs0 += __shfl_xor_sync(0xffffffffu, rs0, 2);
        rs1 += __shfl_xor_sync(0xffffffffu, rs1, 1);
        rs1 += __shfl_xor_sync(0xffffffffu, rs1, 2);
        l0 = l0 * c0 + rs0;
        l1 = l1 * c1 + rs1;
#pragma unroll
        for (int nt = 0; nt < 8; nt++) {
            o[nt][0] *= c0; o[nt][1] *= c0;
            o[nt][2] *= c1; o[nt][3] *= c1;
        }

        // ---- O += P V  (P via C->A fragment identity, hi/lo x3) ----
#pragma unroll
        for (int kf = 0; kf < 4; kf++) {
            uint32_t ph[4], pl[4];
            pack_hilo2(s[2 * kf][0],     s[2 * kf][1],     ph[0], pl[0]);
            pack_hilo2(s[2 * kf][2],     s[2 * kf][3],     ph[1], pl[1]);
            pack_hilo2(s[2 * kf + 1][0], s[2 * kf + 1][1], ph[2], pl[2]);
            pack_hilo2(s[2 * kf + 1][2], s[2 * kf + 1][3], ph[3], pl[3]);

            uint32_t vh[4][4], vl[4][4];
#pragma unroll
            for (int g = 0; g < 4; g++) {
                const uint32_t rb = (uint32_t)(g * 16 + bR) * PITCH_B + bK + kf * 32;
                ldsm_x4(vh[g][0], vh[g][1], vh[g][2], vh[g][3], sbase + FVH + rb);
                ldsm_x4(vl[g][0], vl[g][1], vl[g][2], vl[g][3], sbase + FVL + rb);
            }
#pragma unroll
            for (int nt = 0; nt < 8; nt++) {
                const int ng = nt >> 1;
                const int rp = (nt & 1) * 2;
                mma_16816(o[nt], ph, vh[ng][rp], vh[ng][rp + 1]);
                mma_16816(o[nt], ph, vl[ng][rp], vl[ng][rp + 1]);
                mma_16816(o[nt], pl, vh[ng][rp], vh[ng][rp + 1]);
            }
        }
    }

    // ---- normalize + write O ----
    const float i0 = 1.0f / l0;
    const float i1 = 1.0f / l1;
    const int r0 = qb * 64 + warp * 16 + (lane >> 2);
#pragma unroll
    for (int nt = 0; nt < 8; nt++) {
        const int col = h * DHEAD + nt * 8 + (lane & 3) * 2;
        *(float2*)(g_O + ((size_t)(b * NLAT + r0)) * DIMM + col) =
            make_float2(o[nt][0] * i0, o[nt][1] * i0);
        *(float2*)(g_O + ((size_t)(b * NLAT + r0 + 8)) * DIMM + col) =
            make_float2(o[nt][2] * i1, o[nt][3] * i1);
    }
}

// ---------------------------------------------------------------------------
// Launch
// ---------------------------------------------------------------------------
extern "C" void kernel_launch(void* const* d_in, const int* in_sizes, int n_in,
                              void* d_out, int out_size)
{
    const float* x    = (const float*)d_in[0];
    const float* ctx  = (const float*)d_in[1];
    const float* Wq   = (const float*)d_in[2];
    const float* Wkv  = (const float*)d_in[3];
    const float* Wout = (const float*)d_in[4];
    float* out = (float*)d_out;

    cudaFuncSetAttribute(flash_mma,
                         cudaFuncAttributeMaxDynamicSharedMemorySize, FLASH_SMEM);
    cudaFuncSetAttribute(mm_gemm<0>,
                         cudaFuncAttributeMaxDynamicSharedMemorySize, MM_SMEM);
    cudaFuncSetAttribute(mm_gemm<1>,
                         cudaFuncAttributeMaxDynamicSharedMemorySize, MM_SMEM);
    cudaFuncSetAttribute(mm_gemm<2>,
                         cudaFuncAttributeMaxDynamicSharedMemorySize, MM_SMEM);

    // KV projection: [18432 x 512] @ Wkv[1024 x 512]^T -> g_K | g_V
    mm_gemm<1><<<dim3(1024 / 128, ROWS_KV / 128), 256, MM_SMEM>>>(x, ctx, Wkv, nullptr);
    // Q projection: [2048 x 512] @ Wq[512 x 512]^T -> g_Q
    mm_gemm<0><<<dim3(512 / 128, ROWS_Q / 128), 256, MM_SMEM>>>(x, nullptr, Wq, nullptr);
    // Attention -> g_O
    flash_mma<<<dim3(NLAT / 64, HEADS, B_), 128, FLASH_SMEM>>>();
    // Output projection: g_O @ Wout[512 x 512]^T -> out
    mm_gemm<2><<<dim3(512 / 128, ROWS_Q / 128), 256, MM_SMEM>>>(nullptr, nullptr, Wout, out);
}